// round 8
// baseline (speedup 1.0000x reference)
#include <cuda_runtime.h>
#include <math.h>
#include <float.h>

typedef unsigned long long u64;

// ---------------- problem constants ----------------
constexpr int N  = 8;
constexpr int C  = 64;
constexpr int T  = 256;
constexpr int VQ = 90;
constexpr int VK = 50;
constexpr int S  = 4;
constexpr int L  = 4;
constexpr int TQ = T - L;        // 252
constexpr int SC = S * C;        // 256
constexpr int MQ = TQ * VQ;      // 22680
constexpr int MK = T * VK;       // 12800
constexpr int MO = T * VQ;       // 23040
constexpr int NS = N * S;        // 32
constexpr int NCHUNK = 8;        // c-chunks in att kernel

// ---------------- scratch (device globals) ----------------
__device__ float g_q[(size_t)N * SC * MQ];
__device__ float g_k[(size_t)N * SC * MK];
__device__ float g_v[(size_t)N * C * MK];
__device__ float g_w2[(size_t)NS * C * MK];     // w2[n,s,o,t,u]
__device__ float g_yp[(size_t)N * C * MO];
__device__ float g_dp[(size_t)N * C * MO];
__device__ float g_att_raw[(size_t)(L + 1) * NS * NCHUNK * VQ * VK];
__device__ float g_att[(size_t)NS * VQ * VK];
__device__ float g_wperm[SC * C];
__device__ float g_stats[4 * C];

// ---------------- f32x2 packed helpers ----------------
__device__ __forceinline__ u64 pack2(float lo, float hi) {
    u64 r; asm("mov.b64 %0, {%1, %2};" : "=l"(r) : "f"(lo), "f"(hi)); return r;
}
__device__ __forceinline__ u64 dup2(float v) {
    u64 r; asm("mov.b64 %0, {%1, %1};" : "=l"(r) : "f"(v)); return r;
}
__device__ __forceinline__ void fma2(u64& d, u64 a, u64 b) {
    asm("fma.rn.f32x2 %0, %1, %2, %0;" : "+l"(d) : "l"(a), "l"(b));
}
__device__ __forceinline__ float2 unpack2(u64 v) {
    float2 f; asm("mov.b64 {%0, %1}, %2;" : "=f"(f.x), "=f"(f.y) : "l"(v)); return f;
}

// ---------------- small init kernels ----------------
__global__ void zero_kernel() {
    if (threadIdx.x < 4 * C) g_stats[threadIdx.x] = 0.f;
}
__global__ void perm_kernel(const float* __restrict__ Wout) {
    int i = blockIdx.x * 256 + threadIdx.x;
    if (i < SC * C) {
        int row = i / C, cc = i % C;
        int s = row >> 6, o = row & 63;
        g_wperm[i] = Wout[o * SC + s * C + cc];
    }
}

// ---------------- conv1x1 GEMM (packed f32x2, scalar W in smem) ----------------
// OUT[z] = W[sIdx](CO x CIN) @ X[n](CIN x M) (+ b); z = n*ZS + sIdx.
template <int CO, int CIN>
__global__ __launch_bounds__(256, 2) void proj_gemm(
    const float* __restrict__ X, const float* __restrict__ W,
    const float* __restrict__ b, float* __restrict__ OUT,
    int M, int xRow, long long xBatch, long long oBatch,
    int ZS, int wStride)
{
    constexpr int BO = 64, BC = 256, KT = 16;
    __shared__ __align__(16) float Ws[KT][BO];        // scalar weights
    __shared__ __align__(16) float Xs[KT][BC + 4];

    const int z = blockIdx.z;
    const int n = z / ZS;
    const int sIdx = z % ZS;
    const int o0 = blockIdx.y * BO;
    const int c0 = blockIdx.x * BC;
    const float* Xn = X + (long long)n * xBatch;
    const float* Wz = W + (long long)sIdx * wStride;
    float* On = OUT + (long long)z * oBatch;

    const int tid = threadIdx.x;
    const int tx = tid & 31;       // 32 col groups * 8 cols
    const int ty = tid >> 5;       // 8 row groups * 8 outs

    u64 acc[8][4];
#pragma unroll
    for (int i = 0; i < 8; i++)
#pragma unroll
        for (int j = 0; j < 4; j++) acc[i][j] = 0ull;

    for (int k0 = 0; k0 < CIN; k0 += KT) {
#pragma unroll
        for (int idx = tid; idx < KT * BO; idx += 256) {
            int oo = idx & 63, kk = idx >> 6;
            Ws[kk][oo] = Wz[(o0 + oo) * CIN + k0 + kk];
        }
#pragma unroll
        for (int idx = tid; idx < KT * (BC / 4); idx += 256) {
            int kk = idx >> 6;             // BC/4 = 64
            int c4 = idx & 63;
            int col = c0 + c4 * 4;
            float4 xv = make_float4(0.f, 0.f, 0.f, 0.f);
            if (col < M) xv = *(const float4*)(Xn + (long long)(k0 + kk) * xRow + col);
            *(float4*)&Xs[kk][c4 * 4] = xv;
        }
        __syncthreads();
#pragma unroll
        for (int kk = 0; kk < KT; kk++) {
            float4 wa = *(const float4*)&Ws[kk][ty * 8];
            float4 wb = *(const float4*)&Ws[kk][ty * 8 + 4];
            u64 wv[8] = {dup2(wa.x), dup2(wa.y), dup2(wa.z), dup2(wa.w),
                         dup2(wb.x), dup2(wb.y), dup2(wb.z), dup2(wb.w)};
            const ulonglong2* xp = (const ulonglong2*)&Xs[kk][tx * 8];
            ulonglong2 x01 = xp[0], x23 = xp[1];
            u64 bv[4] = {x01.x, x01.y, x23.x, x23.y};
#pragma unroll
            for (int i = 0; i < 8; i++)
#pragma unroll
                for (int j = 0; j < 4; j++) fma2(acc[i][j], wv[i], bv[j]);
        }
        __syncthreads();
    }
#pragma unroll
    for (int i = 0; i < 8; i++) {
        int o = o0 + ty * 8 + i;
        float bias = b ? b[o] : 0.f;
        float* orow = On + (long long)o * M + c0 + tx * 8;
        float2 p0 = unpack2(acc[i][0]), p1 = unpack2(acc[i][1]);
        float2 p2 = unpack2(acc[i][2]), p3 = unpack2(acc[i][3]);
        float4 v0 = make_float4(p0.x + bias, p0.y + bias, p1.x + bias, p1.y + bias);
        float4 v1 = make_float4(p2.x + bias, p2.y + bias, p3.x + bias, p3.y + bias);
        int col = c0 + tx * 8;
        if (col < M)     *(float4*)orow       = v0;
        if (col + 4 < M) *(float4*)(orow + 4) = v1;
    }
}

// ---------------- multi-lag attention scores (all 5 lags in one pass) ------------
// partial[l][ns][chunk][u][v] = sum over 8 c's and all t of q[t]*k[t+l], scaled.
// Thread tile: 5 u scalars x 1 v pair x 5 lags = 25 FFMA2 per t-step.
// k rows held in a 5-deep register window -> 1 new LDS.64 per step covers all lags.
__global__ __launch_bounds__(480) void att_kernel() {
    constexpr int TT = 21;                    // 252 = 12 * 21
    constexpr int KP = 52;                    // padded VK pitch (floats)
    __shared__ __align__(16) float qs[TT][VQ];
    __shared__ __align__(16) float ks[TT + L][KP];

    const int ns = blockIdx.x, chunk = blockIdx.y;
    const int n = ns >> 2, s = ns & 3;
    const int tid = threadIdx.x;
    const bool active = tid < 450;
    const int u0 = (tid / 25) * 5;            // 18 u-groups of 5 scalars
    const int v0 = (tid % 25) * 2;            // 25 v pairs

    u64 acc[L + 1][5];
#pragma unroll
    for (int l = 0; l <= L; l++)
#pragma unroll
        for (int i = 0; i < 5; i++) acc[l][i] = 0ull;

    const float* qb = g_q + (size_t)(n * SC + s * C) * MQ;
    const float* kb = g_k + (size_t)(n * SC + s * C) * MK;

    for (int c = chunk * 8; c < chunk * 8 + 8; c++) {
        const float* qc = qb + (size_t)c * MQ;
        const float* kc = kb + (size_t)c * MK;
        for (int t0 = 0; t0 < TQ; t0 += TT) {
            const float* qp = qc + t0 * VQ;   // contiguous TT*VQ floats
            const float* kp = kc + t0 * VK;   // contiguous (TT+L)*VK floats
            for (int idx = tid; idx < TT * VQ; idx += 480)
                qs[idx / VQ][idx % VQ] = qp[idx];
            for (int idx = tid; idx < (TT + L) * VK; idx += 480)
                ks[idx / VK][idx % VK] = kp[idx];
            __syncthreads();
            if (active) {
                u64 kw0 = *(const u64*)&ks[0][v0];
                u64 kw1 = *(const u64*)&ks[1][v0];
                u64 kw2 = *(const u64*)&ks[2][v0];
                u64 kw3 = *(const u64*)&ks[3][v0];
#pragma unroll
                for (int tt = 0; tt < TT; tt++) {
                    u64 kw4 = *(const u64*)&ks[tt + L][v0];
#pragma unroll
                    for (int i = 0; i < 5; i++) {
                        u64 qd = dup2(qs[tt][u0 + i]);
                        fma2(acc[0][i], qd, kw0);
                        fma2(acc[1][i], qd, kw1);
                        fma2(acc[2][i], qd, kw2);
                        fma2(acc[3][i], qd, kw3);
                        fma2(acc[4][i], qd, kw4);
                    }
                    kw0 = kw1; kw1 = kw2; kw2 = kw3; kw3 = kw4;
                }
            }
            __syncthreads();
        }
    }
    if (active) {
        const float inv_scale = rsqrtf((float)(C * TQ));
#pragma unroll
        for (int l = 0; l <= L; l++) {
            float* outp = g_att_raw + ((size_t)(l * NS + ns) * NCHUNK + chunk) * (VQ * VK);
#pragma unroll
            for (int i = 0; i < 5; i++) {
                float2 p = unpack2(acc[l][i]);
                outp[(u0 + i) * VK + v0]     = p.x * inv_scale;
                outp[(u0 + i) * VK + v0 + 1] = p.y * inv_scale;
            }
        }
    }
}

// ---------------- reduce chunks, (max+mean)/2 over lags, softmax over v ----------
__global__ void softmax_kernel() {
    const int warp = (blockIdx.x * blockDim.x + threadIdx.x) >> 5;
    const int lane = threadIdx.x & 31;
    if (warp >= NS * VQ) return;
    const int ns = warp / VQ, u = warp % VQ;

    float p[2];
#pragma unroll
    for (int h = 0; h < 2; h++) {
        int v = lane + h * 32;
        p[h] = -FLT_MAX;
        if (v < VK) {
            float m = -FLT_MAX, sm = 0.f;
#pragma unroll
            for (int l = 0; l <= L; l++) {
                float a = 0.f;
#pragma unroll
                for (int ch = 0; ch < NCHUNK; ch++)
                    a += g_att_raw[((size_t)(l * NS + ns) * NCHUNK + ch) * (VQ * VK) + u * VK + v];
                m = fmaxf(m, a);
                sm += a;
            }
            p[h] = 0.5f * (m + sm * (1.0f / (L + 1)));
        }
    }
    float rmax = fmaxf(p[0], p[1]);
#pragma unroll
    for (int o = 16; o; o >>= 1) rmax = fmaxf(rmax, __shfl_xor_sync(0xffffffffu, rmax, o));
    float e[2], ssum = 0.f;
#pragma unroll
    for (int h = 0; h < 2; h++) {
        int v = lane + h * 32;
        e[h] = (v < VK) ? expf(p[h] - rmax) : 0.f;
        ssum += e[h];
    }
#pragma unroll
    for (int o = 16; o; o >>= 1) ssum += __shfl_xor_sync(0xffffffffu, ssum, o);
    float inv = 1.f / ssum;
#pragma unroll
    for (int h = 0; h < 2; h++) {
        int v = lane + h * 32;
        if (v < VK) g_att[(size_t)ns * VQ * VK + u * VK + v] = e[h] * inv;
    }
}

// ---------------- yp[n,o,t,vq] = bout[o] + sum_{s,u} att[n,s,vq,u]*w2[n,s,o,t,u] --
__global__ __launch_bounds__(256, 2) void mix_kernel(const float* __restrict__ bout) {
    constexpr int BR = 128, KH = 25;          // VK processed in 2 halves of 25
    __shared__ __align__(16) float Ast[KH][BR + 4];   // w2 transposed [u][row]
    __shared__ __align__(16) float Bs[KH][VQ + 2];    // att scalar

    const int n = blockIdx.y;
    const int r0 = blockIdx.x * BR;           // row = o*T + t
    const int o = r0 / T;                     // constant within block (128 | 256)
    const int tid = threadIdx.x;
    const bool act = tid < 240;
    const int rr0 = (tid / 15) * 8;           // 16 row groups of 8 (4 pairs)
    const int vq0 = (tid % 15) * 6;           // 15 vq groups of 6

    u64 acc[4][6];
#pragma unroll
    for (int i = 0; i < 4; i++)
#pragma unroll
        for (int j = 0; j < 6; j++) acc[i][j] = 0ull;

    for (int s = 0; s < S; s++) {
        const float* ab = g_att + (size_t)(n * S + s) * VQ * VK;
        const float* wb = g_w2 + (size_t)(n * S + s) * C * MK + (size_t)r0 * VK;
        for (int h = 0; h < 2; h++) {
            for (int idx = tid; idx < VQ * KH; idx += 256) {
                int vq = idx / KH, uu = idx % KH;
                Bs[uu][vq] = ab[vq * VK + h * KH + uu];
            }
            for (int idx = tid; idx < BR * KH; idx += 256) {
                int rr = idx / KH, uu = idx % KH;
                Ast[uu][rr] = wb[rr * VK + h * KH + uu];
            }
            __syncthreads();
            if (act) {
#pragma unroll 5
                for (int uu = 0; uu < KH; uu++) {
                    const ulonglong2* ap = (const ulonglong2*)&Ast[uu][rr0];
                    ulonglong2 a01 = ap[0], a23 = ap[1];
                    u64 av[4] = {a01.x, a01.y, a23.x, a23.y};
                    u64 bv[6];
#pragma unroll
                    for (int j = 0; j < 6; j++) bv[j] = dup2(Bs[uu][vq0 + j]);
#pragma unroll
                    for (int i = 0; i < 4; i++)
#pragma unroll
                        for (int j = 0; j < 6; j++) fma2(acc[i][j], av[i], bv[j]);
                }
            }
            __syncthreads();
        }
    }
    if (act) {
        const float bias = bout[o];
        float* yb = g_yp + (size_t)n * C * MO + (size_t)r0 * VQ;
#pragma unroll
        for (int i = 0; i < 4; i++)
#pragma unroll
            for (int j = 0; j < 6; j++) {
                float2 p = unpack2(acc[i][j]);
                yb[(size_t)(rr0 + 2 * i)     * VQ + vq0 + j] = p.x + bias;
                yb[(size_t)(rr0 + 2 * i + 1) * VQ + vq0 + j] = p.y + bias;
            }
    }
}

// ---------------- BN statistics ----------------
__global__ void stats_kernel() {
    const int co = blockIdx.x, n = blockIdx.y;
    const float* a = g_yp + (size_t)(n * C + co) * MO;
    const float* d = g_dp + (size_t)(n * C + co) * MO;
    float s1 = 0, s2 = 0, s3 = 0, s4 = 0;
    for (int i = threadIdx.x; i < MO; i += blockDim.x) {
        float x = a[i]; s1 += x; s2 += x * x;
        float z = d[i]; s3 += z; s4 += z * z;
    }
#pragma unroll
    for (int o = 16; o; o >>= 1) {
        s1 += __shfl_xor_sync(0xffffffffu, s1, o);
        s2 += __shfl_xor_sync(0xffffffffu, s2, o);
        s3 += __shfl_xor_sync(0xffffffffu, s3, o);
        s4 += __shfl_xor_sync(0xffffffffu, s4, o);
    }
    __shared__ float sm[8][4];
    int wid = threadIdx.x >> 5, lane = threadIdx.x & 31;
    if (lane == 0) { sm[wid][0] = s1; sm[wid][1] = s2; sm[wid][2] = s3; sm[wid][3] = s4; }
    __syncthreads();
    if (threadIdx.x == 0) {
        float t1 = 0, t2 = 0, t3 = 0, t4 = 0;
        for (int w = 0; w < 8; w++) { t1 += sm[w][0]; t2 += sm[w][1]; t3 += sm[w][2]; t4 += sm[w][3]; }
        atomicAdd(&g_stats[co],         t1);
        atomicAdd(&g_stats[C + co],     t2);
        atomicAdd(&g_stats[2 * C + co], t3);
        atomicAdd(&g_stats[3 * C + co], t4);
    }
}

// ---------------- BN + add + leaky_relu ----------------
__global__ void final_kernel(const float* __restrict__ go, const float* __restrict__ bo,
                             const float* __restrict__ gd, const float* __restrict__ bd,
                             float* __restrict__ out) {
    long long i = (long long)blockIdx.x * blockDim.x + threadIdx.x;
    if (i >= (long long)N * C * MO) return;
    int co = (int)((i / MO) % C);
    const float cnt = (float)N * (float)MO;
    float my = g_stats[co] / cnt;
    float vy = g_stats[C + co] / cnt - my * my;
    float md = g_stats[2 * C + co] / cnt;
    float vd = g_stats[3 * C + co] / cnt - md * md;
    float y = (g_yp[i] - my) * rsqrtf(vy + 1e-5f) * go[co] + bo[co];
    float d = (g_dp[i] - md) * rsqrtf(vd + 1e-5f) * gd[co] + bd[co];
    float z = y + d;
    out[i] = z > 0.f ? z : 0.1f * z;
}

// ---------------- launch ----------------
extern "C" void kernel_launch(void* const* d_in, const int* in_sizes, int n_in,
                              void* d_out, int out_size) {
    const float* x_q   = (const float*)d_in[0];
    const float* x_k   = (const float*)d_in[1];
    const float* x_v   = (const float*)d_in[2];
    const float* Wq    = (const float*)d_in[3];
    const float* bq    = (const float*)d_in[4];
    const float* Wk    = (const float*)d_in[5];
    const float* bk    = (const float*)d_in[6];
    const float* Wv    = (const float*)d_in[7];
    const float* bv    = (const float*)d_in[8];
    const float* Wout  = (const float*)d_in[9];
    const float* bout  = (const float*)d_in[10];
    const float* g_out = (const float*)d_in[11];
    const float* b_out = (const float*)d_in[12];
    const float* Wdown = (const float*)d_in[13];
    const float* bdown = (const float*)d_in[14];
    const float* g_dn  = (const float*)d_in[15];
    const float* b_dn  = (const float*)d_in[16];
    float* out = (float*)d_out;

    float *pq, *pk, *pv, *pw2, *pyp, *pdp, *pwperm;
    cudaGetSymbolAddress((void**)&pq,    g_q);
    cudaGetSymbolAddress((void**)&pk,    g_k);
    cudaGetSymbolAddress((void**)&pv,    g_v);
    cudaGetSymbolAddress((void**)&pw2,   g_w2);
    cudaGetSymbolAddress((void**)&pyp,   g_yp);
    cudaGetSymbolAddress((void**)&pdp,   g_dp);
    cudaGetSymbolAddress((void**)&pwperm, g_wperm);

    zero_kernel<<<1, 256>>>();
    perm_kernel<<<(SC * C + 255) / 256, 256>>>(Wout);

    // projections: q (truncated window = contiguous column prefix), k, v
    proj_gemm<SC, C><<<dim3((MQ + 255) / 256, SC / 64, N), 256>>>(
        x_q, Wq, bq, pq, MQ, MO, (long long)C * MO, (long long)SC * MQ, 1, 0);
    proj_gemm<SC, C><<<dim3(MK / 256, SC / 64, N), 256>>>(
        x_k, Wk, bk, pk, MK, MK, (long long)C * MK, (long long)SC * MK, 1, 0);
    proj_gemm<C, C><<<dim3(MK / 256, 1, N), 256>>>(
        x_v, Wv, bv, pv, MK, MK, (long long)C * MK, (long long)C * MK, 1, 0);

    // multi-lag scores (all lags fused) + softmax
    att_kernel<<<dim3(NS, NCHUNK), 480>>>();
    softmax_kernel<<<(NS * VQ) / 8, 256>>>();

    // w2[n,s] = Wperm[s] @ v[n]  (batched over z = n*4+s)
    proj_gemm<C, C><<<dim3(MK / 256, 1, NS), 256>>>(
        pv, pwperm, nullptr, pw2, MK, MK, (long long)C * MK, (long long)C * MK, S, C * C);

    // yp = att-weighted mix of w2 (+bout), and the residual down conv
    mix_kernel<<<dim3(C * T / 128, N), 256>>>(bout);
    proj_gemm<C, C><<<dim3(MO / 256, 1, N), 256>>>(
        x_q, Wdown, bdown, pdp, MO, MO, (long long)C * MO, (long long)C * MO, 1, 0);

    // BN stats + fused epilogue
    stats_kernel<<<dim3(C, N), 256>>>();
    final_kernel<<<((long long)N * C * MO + 255) / 256, 256>>>(g_out, b_out, g_dn, b_dn, out);
}